// round 1
// baseline (speedup 1.0000x reference)
#include <cuda_runtime.h>
#include <math_constants.h>

#define S_TOT 2048
#define B_DIM 64
#define N_DIM 256
#define EPSV 0.01f
#define INV_EPS 100.0f
#define THRESH 0.1f
#define MAX_ITER 100
#define LOG_EPS 1e-8f

// Global scratch: E0_ij = exp((Cmin - C_ij)/eps), identical for all samples.
__device__ float g_E0[B_DIM * N_DIM];
__device__ float g_Cmin;

// ---------------------------------------------------------------------------
// Init kernel: compute Cmin and E0 from C (once per launch, deterministic).
// ---------------------------------------------------------------------------
__global__ void ot_init_kernel(const float* __restrict__ C) {
    __shared__ float sred[8];
    __shared__ float scmin;
    const int tid = threadIdx.x;
    const int l = tid & 31, w = tid >> 5;

    float m = 3.402823466e38f;
    for (int k = tid; k < B_DIM * N_DIM; k += 256)
        m = fminf(m, C[k]);
    #pragma unroll
    for (int o = 16; o; o >>= 1)
        m = fminf(m, __shfl_xor_sync(0xFFFFFFFFu, m, o));
    if (l == 0) sred[w] = m;
    __syncthreads();
    if (tid == 0) {
        float mm = sred[0];
        #pragma unroll
        for (int k = 1; k < 8; k++) mm = fminf(mm, sred[k]);
        scmin = mm;
        g_Cmin = mm;
    }
    __syncthreads();
    const float cmin = scmin;
    for (int k = tid; k < B_DIM * N_DIM; k += 256)
        g_E0[k] = __expf((cmin - C[k]) * INV_EPS);
}

// ---------------------------------------------------------------------------
// Main kernel: one block (256 threads) per sample. Runs Sinkhorn until the
// per-sample err (sum_b |du|) drops below THRESH (matches the reference's
// global criterion for this problem: all samples cross at the same iteration),
// then writes out[s,n] = sum_b pi[s,b,n] * mu[s,b].
// ---------------------------------------------------------------------------
extern "C" __global__ void __launch_bounds__(256)
ot_main_kernel(const float* __restrict__ mu,
               const float* __restrict__ nu,
               float* __restrict__ out) {
    extern __shared__ float sm[];
    float* sE0    = sm;            // [16384]  E0 matrix (row-major, B x N)
    float* sev    = sm + 16384;    // [256]    exp((v_j - m_v)/eps)
    float* su     = sm + 16640;    // [64]     current u
    float* seu    = sm + 16704;    // [64]     exp((u_i - m_u)/eps)
    float* slogmu = sm + 16768;    // [64]     log(mu + LOG_EPS)
    float* smu    = sm + 16832;    // [64]     mu
    float* sdu    = sm + 16896;    // [64]     |du| per row (also reused as weights)
    float* sred   = sm + 16960;    // [16]     reduction scratch; [8]=err [9]=m_u

    const int s   = blockIdx.x;
    const int tid = threadIdx.x;
    const int l   = tid & 31;
    const int w   = tid >> 5;

    // Stage E0 into shared (64KB, float4 coalesced).
    {
        const float4* g4 = reinterpret_cast<const float4*>(g_E0);
        float4* s4 = reinterpret_cast<float4*>(sE0);
        #pragma unroll
        for (int k = 0; k < 16; k++)
            s4[tid + 256 * k] = g4[tid + 256 * k];
    }
    if (tid < B_DIM) {
        float m = mu[s * B_DIM + tid];
        smu[tid]    = m;
        slogmu[tid] = __logf(m + LOG_EPS);
        su[tid]     = 0.0f;
    }
    const float lognu = __logf(nu[s * N_DIM + tid] + LOG_EPS);
    sev[tid] = 1.0f;              // v = 0, m_v = 0 -> ev = 1
    const float cmin = g_Cmin;
    __syncthreads();

    float m_v = 0.0f;
    float m_u = 0.0f;
    float err = CUDART_INF_F;

    for (int it = 0; it < MAX_ITER; ++it) {
        // ---- u update: warp w handles rows 8w..8w+7 ----
        const float4 evA = reinterpret_cast<const float4*>(sev)[l];
        const float4 evB = reinterpret_cast<const float4*>(sev)[32 + l];
        #pragma unroll
        for (int r = 0; r < 8; ++r) {
            const int row = (w << 3) + r;
            const float4* e4 = reinterpret_cast<const float4*>(sE0 + (row << 8));
            const float4 a = e4[l];
            const float4 b = e4[32 + l];
            float p = a.x * evA.x + a.y * evA.y + a.z * evA.z + a.w * evA.w
                    + b.x * evB.x + b.y * evB.y + b.z * evB.z + b.w * evB.w;
            #pragma unroll
            for (int o = 16; o; o >>= 1)
                p += __shfl_xor_sync(0xFFFFFFFFu, p, o);
            if (l == r) {
                // u_new = eps*log_mu - (m_v - cmin) - eps*log(sum)
                float unew = EPSV * slogmu[row] - (m_v - cmin) - EPSV * __logf(p);
                sdu[row] = fabsf(unew - su[row]);
                su[row]  = unew;
            }
        }
        __syncthreads();

        // ---- reduce err = sum |du|, m_u = max u ----
        if (w == 0) {
            float d  = sdu[l] + sdu[l + 32];
            float um = fmaxf(su[l], su[l + 32]);
            #pragma unroll
            for (int o = 16; o; o >>= 1) {
                d += __shfl_xor_sync(0xFFFFFFFFu, d, o);
                um = fmaxf(um, __shfl_xor_sync(0xFFFFFFFFu, um, o));
            }
            if (l == 0) { sred[8] = d; sred[9] = um; }
        }
        __syncthreads();
        err = sred[8];
        m_u = sred[9];
        if (tid < B_DIM)
            seu[tid] = __expf((su[tid] - m_u) * INV_EPS);
        __syncthreads();

        // ---- v update: thread tid owns column j = tid ----
        {
            const float* col = sE0 + tid;
            float acc0 = 0.0f, acc1 = 0.0f;
            #pragma unroll
            for (int i = 0; i < B_DIM; i += 4) {
                const float4 e = reinterpret_cast<const float4*>(seu)[i >> 2];
                acc0 = fmaf(col[(i    ) << 8], e.x, acc0);
                acc1 = fmaf(col[(i + 1) << 8], e.y, acc1);
                acc0 = fmaf(col[(i + 2) << 8], e.z, acc0);
                acc1 = fmaf(col[(i + 3) << 8], e.w, acc1);
            }
            const float accv = acc0 + acc1;
            const float v = EPSV * lognu - (m_u - cmin) - EPSV * __logf(accv);

            // block-reduce m_v
            float mv = v;
            #pragma unroll
            for (int o = 16; o; o >>= 1)
                mv = fmaxf(mv, __shfl_xor_sync(0xFFFFFFFFu, mv, o));
            if (l == 0) sred[w] = mv;
            __syncthreads();
            mv = sred[0];
            #pragma unroll
            for (int k = 1; k < 8; k++) mv = fmaxf(mv, sred[k]);
            m_v = mv;
            sev[tid] = __expf((v - m_v) * INV_EPS);
        }
        __syncthreads();

        // Reference: body always completes (u AND v updated), THEN cond checks err.
        if (err < THRESH) break;
    }

    // ---- epilogue: out[s,n] = S * ev_n * sum_b E0_bn * eu_b * mu_b ----
    if (tid < B_DIM)
        sdu[tid] = seu[tid] * smu[tid];   // reuse sdu as weights
    __syncthreads();
    {
        const float* col = sE0 + tid;
        float acc0 = 0.0f, acc1 = 0.0f;
        #pragma unroll
        for (int i = 0; i < B_DIM; i += 4) {
            const float4 e = reinterpret_cast<const float4*>(sdu)[i >> 2];
            acc0 = fmaf(col[(i    ) << 8], e.x, acc0);
            acc1 = fmaf(col[(i + 1) << 8], e.y, acc1);
            acc0 = fmaf(col[(i + 2) << 8], e.z, acc0);
            acc1 = fmaf(col[(i + 3) << 8], e.w, acc1);
        }
        const float scale = __expf((m_u + m_v - cmin) * INV_EPS);
        out[s * N_DIM + tid] = scale * sev[tid] * (acc0 + acc1);
    }
}

// ---------------------------------------------------------------------------
// Launch
// ---------------------------------------------------------------------------
extern "C" void kernel_launch(void* const* d_in, const int* in_sizes, int n_in,
                              void* d_out, int out_size) {
    const float* mu = nullptr;
    const float* nu = nullptr;
    const float* C  = nullptr;
    for (int i = 0; i < n_in; ++i) {
        if (in_sizes[i] == S_TOT * B_DIM)      mu = (const float*)d_in[i];
        else if (in_sizes[i] == S_TOT * N_DIM) nu = (const float*)d_in[i];
        else if (in_sizes[i] == B_DIM * N_DIM) C  = (const float*)d_in[i];
    }
    float* out = (float*)d_out;

    const int smem_bytes = 16976 * sizeof(float);  // ~66.3 KB
    cudaFuncSetAttribute(ot_main_kernel,
                         cudaFuncAttributeMaxDynamicSharedMemorySize, smem_bytes);

    ot_init_kernel<<<1, 256>>>(C);
    ot_main_kernel<<<S_TOT, 256, smem_bytes>>>(mu, nu, out);
}